// round 1
// baseline (speedup 1.0000x reference)
#include <cuda_runtime.h>
#include <math.h>

#define BATCH  128
#define HIDDEN 1024
#define EMBED  512
#define VOCAB  32000
#define MAXLEN 48
#define GATES4 4096
#define NTILES (VOCAB/128)   // 250

// ---------------- persistent scratch (device globals; no allocation) ----------
__device__ float g_h[BATCH*HIDDEN];
__device__ float g_c[BATCH*HIDDEN];
__device__ float g_x[BATCH*EMBED];
__device__ float g_gates[BATCH*GATES4];
__device__ float g_pval[NTILES*BATCH];
__device__ int   g_pidx[NTILES*BATCH];

// ---------------- init: state copy, x0 = embedding[sos], zero out[0] ----------
__global__ void init_kernel(const float* __restrict__ eh, const float* __restrict__ ec,
                            const float* __restrict__ emb, const int* __restrict__ sos,
                            float* __restrict__ out0)
{
    int idx = blockIdx.x * 256 + threadIdx.x;
    if (idx < BATCH*HIDDEN) { g_h[idx] = eh[idx]; g_c[idx] = ec[idx]; }
    if (idx < BATCH*EMBED)  { g_x[idx] = emb[sos[0]*EMBED + (idx & (EMBED-1))]; }
    if (idx < BATCH*VOCAB)  out0[idx] = 0.0f;
}

// ---------------- gates GEMM: C[128 x 4096] = [x|h] @ [w_ih|w_hh]^T -----------
// 64x64 tiles, 256 thr, warp tile 32x16, thread tile 8x2.
__global__ __launch_bounds__(256) void gates_kernel(
    const float* __restrict__ w_ih, const float* __restrict__ w_hh)
{
    __shared__ float As[16][64];
    __shared__ float Bs[16][64];
    const int n0   = blockIdx.x * 64;   // gate-neuron tile
    const int bm0  = blockIdx.y * 64;   // batch tile
    const int t    = threadIdx.x;
    const int warp = t >> 5, lane = t & 31;
    const int wm = warp >> 2, wn = warp & 3;
    const int lm = lane >> 3, ln = lane & 7;
    const int mfrag = wm*32 + lm*8;
    const int nfrag = wn*16 + ln*2;
    const int lc = t & 3, lrow = t >> 2;   // 64 rows x 4 float4-chunks

    float acc[8][2];
#pragma unroll
    for (int i = 0; i < 8; i++) { acc[i][0] = 0.f; acc[i][1] = 0.f; }

    for (int k0 = 0; k0 < 1536; k0 += 16) {
        const float* Ap; const float* Bp; int ka, strd;
        if (k0 < 512) { Ap = g_x; Bp = w_ih; ka = k0;       strd = EMBED;  }
        else          { Ap = g_h; Bp = w_hh; ka = k0 - 512; strd = HIDDEN; }
        float4 va = *(const float4*)&Ap[(bm0 + lrow)*strd + ka + lc*4];
        float4 vb = *(const float4*)&Bp[(n0  + lrow)*strd + ka + lc*4];
        As[lc*4+0][lrow] = va.x; As[lc*4+1][lrow] = va.y;
        As[lc*4+2][lrow] = va.z; As[lc*4+3][lrow] = va.w;
        Bs[lc*4+0][lrow] = vb.x; Bs[lc*4+1][lrow] = vb.y;
        Bs[lc*4+2][lrow] = vb.z; Bs[lc*4+3][lrow] = vb.w;
        __syncthreads();
#pragma unroll
        for (int kk = 0; kk < 16; kk++) {
            float a[8];
            *(float4*)&a[0] = *(const float4*)&As[kk][mfrag];
            *(float4*)&a[4] = *(const float4*)&As[kk][mfrag+4];
            float b0 = Bs[kk][nfrag], b1 = Bs[kk][nfrag+1];
#pragma unroll
            for (int i = 0; i < 8; i++) {
                acc[i][0] = fmaf(a[i], b0, acc[i][0]);
                acc[i][1] = fmaf(a[i], b1, acc[i][1]);
            }
        }
        __syncthreads();
    }
#pragma unroll
    for (int i = 0; i < 8; i++) {
        float2 o = make_float2(acc[i][0], acc[i][1]);
        *(float2*)&g_gates[(bm0 + mfrag + i)*GATES4 + n0 + nfrag] = o;
    }
}

// ---------------- LSTM elementwise update ------------------------------------
__global__ void lstm_kernel(const float* __restrict__ b_ih, const float* __restrict__ b_hh)
{
    int idx = blockIdx.x * 256 + threadIdx.x;     // < 128*1024
    int b = idx >> 10, j = idx & 1023;
    const float* gr = &g_gates[b * GATES4];
    float ig = gr[j]        + b_ih[j]        + b_hh[j];
    float fg = gr[1024 + j] + b_ih[1024 + j] + b_hh[1024 + j];
    float gg = gr[2048 + j] + b_ih[2048 + j] + b_hh[2048 + j];
    float og = gr[3072 + j] + b_ih[3072 + j] + b_hh[3072 + j];
    float i_s = 1.f / (1.f + expf(-ig));
    float f_s = 1.f / (1.f + expf(-fg));
    float g_t = tanhf(gg);
    float o_s = 1.f / (1.f + expf(-og));
    float c = f_s * g_c[idx] + i_s * g_t;
    g_c[idx] = c;
    g_h[idx] = o_s * tanhf(c);
}

// ---------------- logits GEMM: out[t] = h @ w_out^T + b; partial argmax -------
// 128x128 tiles, 256 thr, warp tile 64x32, thread tile 16x4.
__global__ __launch_bounds__(256, 2) void logits_kernel(
    const float* __restrict__ W, const float* __restrict__ bias,
    float* __restrict__ outSlice)
{
    __shared__ float As[16][128];
    __shared__ float Bs[16][128];
    const int n0   = blockIdx.x * 128;
    const int t    = threadIdx.x;
    const int warp = t >> 5, lane = t & 31;
    const int wm = warp >> 2, wn = warp & 3;    // wm: 2 x 64 rows, wn: 4 x 32 cols
    const int lm = lane >> 3, ln = lane & 7;
    const int mfrag = wm*64 + lm*16;
    const int nfrag = wn*32 + ln*4;
    const int lc = t & 3, lrow = t >> 2;        // 64 rows x 4 chunks

    float acc[16][4];
#pragma unroll
    for (int i = 0; i < 16; i++)
#pragma unroll
        for (int j = 0; j < 4; j++) acc[i][j] = 0.f;

    for (int k0 = 0; k0 < HIDDEN; k0 += 16) {
#pragma unroll
        for (int j = 0; j < 2; j++) {
            int m = lrow + j*64;
            float4 va = *(const float4*)&g_h[m*HIDDEN + k0 + lc*4];
            float4 vb = *(const float4*)&W[(size_t)(n0 + m)*HIDDEN + k0 + lc*4];
            As[lc*4+0][m] = va.x; As[lc*4+1][m] = va.y;
            As[lc*4+2][m] = va.z; As[lc*4+3][m] = va.w;
            Bs[lc*4+0][m] = vb.x; Bs[lc*4+1][m] = vb.y;
            Bs[lc*4+2][m] = vb.z; Bs[lc*4+3][m] = vb.w;
        }
        __syncthreads();
#pragma unroll
        for (int kk = 0; kk < 16; kk++) {
            float a[16];
            *(float4*)&a[0]  = *(const float4*)&As[kk][mfrag];
            *(float4*)&a[4]  = *(const float4*)&As[kk][mfrag+4];
            *(float4*)&a[8]  = *(const float4*)&As[kk][mfrag+8];
            *(float4*)&a[12] = *(const float4*)&As[kk][mfrag+12];
            float4 bv = *(const float4*)&Bs[kk][nfrag];
#pragma unroll
            for (int i = 0; i < 16; i++) {
                acc[i][0] = fmaf(a[i], bv.x, acc[i][0]);
                acc[i][1] = fmaf(a[i], bv.y, acc[i][1]);
                acc[i][2] = fmaf(a[i], bv.z, acc[i][2]);
                acc[i][3] = fmaf(a[i], bv.w, acc[i][3]);
            }
        }
        __syncthreads();
    }

    // epilogue: bias add, store, per-row partial argmax over this block's 128 cols
    float4 bb = *(const float4*)&bias[n0 + nfrag];
    float (*redv)[4] = (float(*)[4])&As[0][0];   // reuse smem (post final sync)
    int   (*redi)[4] = (int  (*)[4])&Bs[0][0];

#pragma unroll
    for (int i = 0; i < 16; i++) {
        int m = mfrag + i;
        float v0 = acc[i][0] + bb.x, v1 = acc[i][1] + bb.y;
        float v2 = acc[i][2] + bb.z, v3 = acc[i][3] + bb.w;
        float4 o = make_float4(v0, v1, v2, v3);
        *(float4*)&outSlice[(size_t)m*VOCAB + n0 + nfrag] = o;

        float bvv = v0; int bix = nfrag;
        if (v1 > bvv) { bvv = v1; bix = nfrag+1; }
        if (v2 > bvv) { bvv = v2; bix = nfrag+2; }
        if (v3 > bvv) { bvv = v3; bix = nfrag+3; }
#pragma unroll
        for (int off = 4; off > 0; off >>= 1) {
            float ov = __shfl_down_sync(0xffffffffu, bvv, off, 8);
            int   oi = __shfl_down_sync(0xffffffffu, bix, off, 8);
            if (ov > bvv || (ov == bvv && oi < bix)) { bvv = ov; bix = oi; }
        }
        if (ln == 0) { redv[m][wn] = bvv; redi[m][wn] = bix; }
    }
    __syncthreads();
    if (t < 128) {
        float bvv = redv[t][0]; int bix = redi[t][0];
#pragma unroll
        for (int w = 1; w < 4; w++) {
            float ov = redv[t][w]; int oi = redi[t][w];
            if (ov > bvv || (ov == bvv && oi < bix)) { bvv = ov; bix = oi; }
        }
        g_pval[blockIdx.x * BATCH + t] = bvv;
        g_pidx[blockIdx.x * BATCH + t] = n0 + bix;
    }
}

// ---------------- argmax finalize + embedding gather --------------------------
__global__ void finalize_kernel(const float* __restrict__ emb)
{
    int row = blockIdx.x;
    int t = threadIdx.x;
    __shared__ float sv[256];
    __shared__ int   si[256];
    __shared__ int   nstar;
    float v = -INFINITY; int id = 0x7fffffff;
    if (t < NTILES) { v = g_pval[t*BATCH + row]; id = g_pidx[t*BATCH + row]; }
    sv[t] = v; si[t] = id;
    __syncthreads();
    for (int s = 128; s > 0; s >>= 1) {
        if (t < s) {
            float ov = sv[t+s]; int oi = si[t+s];
            if (ov > sv[t] || (ov == sv[t] && oi < si[t])) { sv[t] = ov; si[t] = oi; }
        }
        __syncthreads();
    }
    if (t == 0) nstar = si[0];
    __syncthreads();
    if (t < EMBED/4) {
        float4 e = *(const float4*)&emb[(size_t)nstar*EMBED + t*4];
        *(float4*)&g_x[row*EMBED + t*4] = e;
    }
}

// ---------------- launch ------------------------------------------------------
extern "C" void kernel_launch(void* const* d_in, const int* in_sizes, int n_in,
                              void* d_out, int out_size)
{
    const float* eh    = (const float*)d_in[0];
    const float* ec    = (const float*)d_in[1];
    const float* emb   = (const float*)d_in[2];
    const float* w_ih  = (const float*)d_in[3];
    const float* w_hh  = (const float*)d_in[4];
    const float* b_ih  = (const float*)d_in[5];
    const float* b_hh  = (const float*)d_in[6];
    const float* w_out = (const float*)d_in[7];
    const float* b_out = (const float*)d_in[8];
    const int*   sos   = (const int*)d_in[9];
    float* out = (float*)d_out;

    init_kernel<<<(BATCH*VOCAB + 255)/256, 256>>>(eh, ec, emb, sos, out);
    for (int step = 1; step < MAXLEN; step++) {
        gates_kernel<<<dim3(64, 2), 256>>>(w_ih, w_hh);
        lstm_kernel<<<(BATCH*HIDDEN)/256, 256>>>(b_ih, b_hh);
        logits_kernel<<<NTILES, 256>>>(w_out, b_out, out + (size_t)step*BATCH*VOCAB);
        finalize_kernel<<<BATCH, 256>>>(emb);
    }
}

// round 3
// speedup vs baseline: 1.7019x; 1.7019x over previous
#include <cuda_runtime.h>
#include <cuda_bf16.h>
#include <math.h>
#include <stdint.h>

#define BATCH   128
#define HIDDEN  1024
#define EMBED   512
#define VOCAB   32000
#define MAXLEN  48
#define GATES4  4096
#define KL      1024          // logits K
#define KG      1536          // gates K (512 x + 1024 h)
#define NTILES  250           // logits N tiles of 128
#define STAGE_BYTES 98304     // 6 tiles x 16KB
#define SMEM_BYTES  (2*STAGE_BYTES)

// ---------------- persistent device state (no allocation) --------------------
__device__ __align__(16) __nv_bfloat16 g_a0[BATCH*KG];   // A: cols [0,512)=x, [512,1536)=h
__device__ __align__(16) __nv_bfloat16 g_a1[BATCH*KG];
__device__ __align__(16) __nv_bfloat16 g_a2[BATCH*KG];
__device__ __align__(16) __nv_bfloat16 g_w0[(size_t)VOCAB*KL];
__device__ __align__(16) __nv_bfloat16 g_w1[(size_t)VOCAB*KL];
__device__ __align__(16) __nv_bfloat16 g_w2[(size_t)VOCAB*KL];
__device__ __align__(16) __nv_bfloat16 g_g0[(size_t)GATES4*KG];
__device__ __align__(16) __nv_bfloat16 g_g1[(size_t)GATES4*KG];
__device__ __align__(16) __nv_bfloat16 g_g2[(size_t)GATES4*KG];
__device__ float g_c[BATCH*HIDDEN];
__device__ float g_part[3*BATCH*GATES4];   // split-K partials for gates
__device__ float g_pval[NTILES*BATCH];
__device__ int   g_pidx[NTILES*BATCH];

// ---------------- ptx helpers (base-family PTX only: sm_80+ ops) -------------
__device__ __forceinline__ uint32_t smem_u32(const void* p) {
    uint32_t a;
    asm("{ .reg .u64 t; cvta.to.shared.u64 t, %1; cvt.u32.u64 %0, t; }" : "=r"(a) : "l"(p));
    return a;
}
__device__ __forceinline__ void cpa16(uint32_t dst, const void* src) {
    asm volatile("cp.async.cg.shared.global [%0], [%1], 16;" :: "r"(dst), "l"(src));
}
__device__ __forceinline__ void cpa_commit() {
    asm volatile("cp.async.commit_group;" ::: "memory");
}
template<int N> __device__ __forceinline__ void cpa_wait() {
    asm volatile("cp.async.wait_group %0;" :: "n"(N) : "memory");
}
__device__ __forceinline__ void ldsm4(uint32_t* r, uint32_t addr) {
    asm volatile("ldmatrix.sync.aligned.m8n8.x4.shared.b16 {%0,%1,%2,%3}, [%4];"
                 : "=r"(r[0]), "=r"(r[1]), "=r"(r[2]), "=r"(r[3]) : "r"(addr));
}
__device__ __forceinline__ void mma16816(float* c, const uint32_t* a, uint32_t b0, uint32_t b1) {
    asm volatile(
        "mma.sync.aligned.m16n8k16.row.col.f32.bf16.bf16.f32 "
        "{%0,%1,%2,%3}, {%4,%5,%6,%7}, {%8,%9}, {%0,%1,%2,%3};"
        : "+f"(c[0]), "+f"(c[1]), "+f"(c[2]), "+f"(c[3])
        : "r"(a[0]), "r"(a[1]), "r"(a[2]), "r"(a[3]), "r"(b0), "r"(b1));
}
__device__ __forceinline__ uint32_t swz(uint32_t off) { return off ^ ((off >> 3) & 0x70); }

__device__ __forceinline__ void split3(float x, __nv_bfloat16& a, __nv_bfloat16& b, __nv_bfloat16& c) {
    a = __float2bfloat16(x);
    float r = x - __bfloat162float(a);
    b = __float2bfloat16(r);
    r -= __bfloat162float(b);
    c = __float2bfloat16(r);
}

// ---------------- weight conversion --------------------------------------
__global__ void conv_wout_kernel(const float* __restrict__ w) {
    size_t i4 = ((size_t)blockIdx.x * 256 + threadIdx.x) * 4;
    if (i4 >= (size_t)VOCAB * KL) return;
    float4 v = *(const float4*)&w[i4];
    __nv_bfloat16 a[4], b[4], c[4];
    split3(v.x, a[0], b[0], c[0]); split3(v.y, a[1], b[1], c[1]);
    split3(v.z, a[2], b[2], c[2]); split3(v.w, a[3], b[3], c[3]);
#pragma unroll
    for (int j = 0; j < 4; j++) { g_w0[i4+j] = a[j]; g_w1[i4+j] = b[j]; g_w2[i4+j] = c[j]; }
}
__global__ void conv_wg_kernel(const float* __restrict__ w_ih, const float* __restrict__ w_hh) {
    size_t i4 = ((size_t)blockIdx.x * 256 + threadIdx.x) * 4;
    if (i4 >= (size_t)GATES4 * KG) return;
    int n = (int)(i4 / KG), k = (int)(i4 % KG);
    float4 v;
    if (k < EMBED) v = *(const float4*)&w_ih[(size_t)n*EMBED + k];
    else           v = *(const float4*)&w_hh[(size_t)n*HIDDEN + (k - EMBED)];
    __nv_bfloat16 a[4], b[4], c[4];
    split3(v.x, a[0], b[0], c[0]); split3(v.y, a[1], b[1], c[1]);
    split3(v.z, a[2], b[2], c[2]); split3(v.w, a[3], b[3], c[3]);
#pragma unroll
    for (int j = 0; j < 4; j++) { g_g0[i4+j] = a[j]; g_g1[i4+j] = b[j]; g_g2[i4+j] = c[j]; }
}

// ---------------- init -------------------------------------------------------
__global__ void init_kernel(const float* __restrict__ eh, const float* __restrict__ ec,
                            const float* __restrict__ emb, const int* __restrict__ sos,
                            float* __restrict__ out0)
{
    int idx = blockIdx.x * 256 + threadIdx.x;
    if (idx < BATCH*HIDDEN) {
        int bb = idx >> 10, j = idx & 1023;
        __nv_bfloat16 a, b, c;
        split3(eh[idx], a, b, c);
        g_a0[bb*KG + 512 + j] = a; g_a1[bb*KG + 512 + j] = b; g_a2[bb*KG + 512 + j] = c;
        g_c[idx] = ec[idx];
    }
    if (idx < BATCH*EMBED) {
        int bb = idx >> 9, j = idx & 511;
        __nv_bfloat16 a, b, c;
        split3(emb[(size_t)sos[0]*EMBED + j], a, b, c);
        g_a0[bb*KG + j] = a; g_a1[bb*KG + j] = b; g_a2[bb*KG + j] = c;
    }
    if (idx < BATCH*VOCAB) out0[idx] = 0.0f;
}

// ---------------- split-bf16 HMMA GEMM ---------------------------------------
// C[128 x 128-tile] = sum of 6 split products, fp32 accum (mma.sync m16n8k16).
// MODE 0: gates (split-K over blockIdx.y, write g_part).
// MODE 1: logits (+bias, store to out, fused partial argmax).
template<int KLEN, int AOFF, int MODE>
__global__ __launch_bounds__(256, 1) void hmma_gemm(
    const float* __restrict__ bias, float* __restrict__ out)
{
    extern __shared__ char smem[];
    const uint32_t sbase = smem_u32(smem);
    const int tid  = threadIdx.x;
    const int lane = tid & 31;
    const int warp = tid >> 5;
    const int wm = warp >> 2, wn = warp & 3;
    const int m_base = wm * 64, n_base = wn * 32;
    const int n0     = blockIdx.x * 128;
    const int kStart = (MODE == 0) ? blockIdx.y * KLEN : 0;
    const int BSTRIDE = (MODE == 1) ? KL : KG;
    const int NC = KLEN / 64;

    const __nv_bfloat16* Aptr[3] = { g_a0, g_a1, g_a2 };
    const __nv_bfloat16* Bptr[3];
    if (MODE == 1) { Bptr[0] = g_w0; Bptr[1] = g_w1; Bptr[2] = g_w2; }
    else           { Bptr[0] = g_g0; Bptr[1] = g_g1; Bptr[2] = g_g2; }

    auto load_stage = [&](int buf, int c) {
        uint32_t sdst = sbase + buf * STAGE_BYTES;
        const int k0   = c * 64;
        const int aCol = AOFF + kStart + k0;
        const int bCol = kStart + k0;
#pragma unroll
        for (int i = 0; i < 24; i++) {
            const int tile = i >> 2;
            const int rem = (i * 256 + tid) & 1023;
            const int row = rem >> 3, ch = rem & 7;
            const __nv_bfloat16* src;
            if (tile < 3) src = Aptr[tile] + row * KG + aCol + ch * 8;
            else          src = Bptr[tile-3] + (size_t)(n0 + row) * BSTRIDE + bCol + ch * 8;
            cpa16(sdst + tile * 16384 + swz((uint32_t)(row * 128 + ch * 16)), src);
        }
    };

    float acc[4][4][4];
#pragma unroll
    for (int i = 0; i < 4; i++)
#pragma unroll
        for (int j = 0; j < 4; j++)
#pragma unroll
            for (int q = 0; q < 4; q++) acc[i][j][q] = 0.f;

    load_stage(0, 0);
    cpa_commit();

#pragma unroll 1
    for (int c = 0; c < NC; c++) {
        if (c + 1 < NC) { load_stage((c + 1) & 1, c + 1); cpa_commit(); cpa_wait<1>(); }
        else            { cpa_wait<0>(); }
        __syncthreads();

        const uint32_t sb = sbase + (c & 1) * STAGE_BYTES;
#pragma unroll 1
        for (int t = 0; t < 6; t++) {
            int as_, bs_;
            if (t < 3)      { as_ = t;     bs_ = 0; }
            else if (t < 5) { as_ = t - 3; bs_ = 1; }
            else            { as_ = 0;     bs_ = 2; }
            const uint32_t sA = sb + as_ * 16384;
            const uint32_t sB = sb + 49152 + bs_ * 16384;
#pragma unroll
            for (int ks = 0; ks < 4; ks++) {
                const uint32_t kb = (uint32_t)(ks * 32 + ((lane >> 4) << 4));
                uint32_t a[4][4];
#pragma unroll
                for (int mt = 0; mt < 4; mt++)
                    ldsm4(a[mt], sA + swz((uint32_t)((m_base + mt*16 + (lane & 15)) * 128) + kb));
                uint32_t br[2][4];
#pragma unroll
                for (int nh = 0; nh < 2; nh++)
                    ldsm4(br[nh], sB + swz((uint32_t)((n_base + nh*16 + (lane & 15)) * 128) + kb));
#pragma unroll
                for (int mt = 0; mt < 4; mt++)
#pragma unroll
                    for (int nt = 0; nt < 4; nt++) {
                        const int nh = nt >> 1, hi = nt & 1;
                        mma16816(acc[mt][nt], a[mt], br[nh][hi], br[nh][hi + 2]);
                    }
            }
        }
        __syncthreads();
    }

    // -------------------------- epilogue ------------------------------------
    if (MODE == 0) {
        float* o = g_part + (size_t)blockIdx.y * BATCH * GATES4;
#pragma unroll
        for (int mt = 0; mt < 4; mt++) {
            const int r0 = m_base + mt * 16 + (lane >> 2);
#pragma unroll
            for (int nt = 0; nt < 4; nt++) {
                const int col = n0 + n_base + nt * 8 + (lane & 3) * 2;
                *(float2*)&o[(size_t)r0 * GATES4 + col]       = make_float2(acc[mt][nt][0], acc[mt][nt][1]);
                *(float2*)&o[(size_t)(r0 + 8) * GATES4 + col] = make_float2(acc[mt][nt][2], acc[mt][nt][3]);
            }
        }
    } else {
        float2 bv[4];
#pragma unroll
        for (int nt = 0; nt < 4; nt++)
            bv[nt] = *(const float2*)&bias[n0 + n_base + nt * 8 + (lane & 3) * 2];

        float* rv = (float*)smem;            // reuse stage smem (post-sync)
        int*   ri = (int*)(smem + 4096);

#pragma unroll
        for (int mt = 0; mt < 4; mt++) {
#pragma unroll
            for (int half = 0; half < 2; half++) {
                const int row = m_base + mt * 16 + (lane >> 2) + half * 8;
                float best = -INFINITY; int bidx = 0;
#pragma unroll
                for (int nt = 0; nt < 4; nt++) {
                    const int col = n0 + n_base + nt * 8 + (lane & 3) * 2;
                    float v0 = acc[mt][nt][half*2]   + bv[nt].x;
                    float v1 = acc[mt][nt][half*2+1] + bv[nt].y;
                    *(float2*)&out[(size_t)row * VOCAB + col] = make_float2(v0, v1);
                    if (v0 > best) { best = v0; bidx = col; }
                    if (v1 > best) { best = v1; bidx = col + 1; }
                }
#pragma unroll
                for (int off = 1; off <= 2; off <<= 1) {
                    float ov = __shfl_xor_sync(0xffffffffu, best, off);
                    int   oi = __shfl_xor_sync(0xffffffffu, bidx, off);
                    if (ov > best || (ov == best && oi < bidx)) { best = ov; bidx = oi; }
                }
                if ((lane & 3) == 0) { rv[row * 4 + wn] = best; ri[row * 4 + wn] = bidx; }
            }
        }
        __syncthreads();
        if (tid < 128) {
            float best = rv[tid * 4]; int bidx = ri[tid * 4];
#pragma unroll
            for (int w = 1; w < 4; w++) {
                float ov = rv[tid * 4 + w]; int oi = ri[tid * 4 + w];
                if (ov > best || (ov == best && oi < bidx)) { best = ov; bidx = oi; }
            }
            g_pval[blockIdx.x * BATCH + tid] = best;
            g_pidx[blockIdx.x * BATCH + tid] = bidx;
        }
    }
}

// ---------------- LSTM elementwise (sums split-K partials) -------------------
__global__ void lstm_kernel(const float* __restrict__ b_ih, const float* __restrict__ b_hh)
{
    int idx = blockIdx.x * 256 + threadIdx.x;     // < 128*1024
    int b = idx >> 10, j = idx & 1023;
    const float* P0 = g_part;
    const float* P1 = g_part + BATCH*GATES4;
    const float* P2 = g_part + 2*BATCH*GATES4;
    const int o = b * GATES4 + j;
    float ig = P0[o]        + P1[o]        + P2[o]        + b_ih[j]        + b_hh[j];
    float fg = P0[o+1024]   + P1[o+1024]   + P2[o+1024]   + b_ih[1024+j]   + b_hh[1024+j];
    float gg = P0[o+2048]   + P1[o+2048]   + P2[o+2048]   + b_ih[2048+j]   + b_hh[2048+j];
    float og = P0[o+3072]   + P1[o+3072]   + P2[o+3072]   + b_ih[3072+j]   + b_hh[3072+j];
    float i_s = 1.f / (1.f + expf(-ig));
    float f_s = 1.f / (1.f + expf(-fg));
    float g_t = tanhf(gg);
    float o_s = 1.f / (1.f + expf(-og));
    float cc = f_s * g_c[idx] + i_s * g_t;
    g_c[idx] = cc;
    float h = o_s * tanhf(cc);
    __nv_bfloat16 a, bb2, c2;
    split3(h, a, bb2, c2);
    g_a0[b*KG + 512 + j] = a; g_a1[b*KG + 512 + j] = bb2; g_a2[b*KG + 512 + j] = c2;
}

// ---------------- argmax finalize + embedding gather -------------------------
__global__ void finalize_kernel(const float* __restrict__ emb)
{
    int row = blockIdx.x;
    int t = threadIdx.x;
    __shared__ float sv[256];
    __shared__ int   si[256];
    __shared__ int   nstar;
    float v = -INFINITY; int id = 0x7fffffff;
    if (t < NTILES) { v = g_pval[t*BATCH + row]; id = g_pidx[t*BATCH + row]; }
    sv[t] = v; si[t] = id;
    __syncthreads();
    for (int s = 128; s > 0; s >>= 1) {
        if (t < s) {
            float ov = sv[t+s]; int oi = si[t+s];
            if (ov > sv[t] || (ov == sv[t] && oi < si[t])) { sv[t] = ov; si[t] = oi; }
        }
        __syncthreads();
    }
    if (t == 0) nstar = si[0];
    __syncthreads();
    {
        int j = t * 2;
        float2 e = *(const float2*)&emb[(size_t)nstar*EMBED + j];
        __nv_bfloat16 a, b, c;
        split3(e.x, a, b, c);
        g_a0[row*KG + j] = a; g_a1[row*KG + j] = b; g_a2[row*KG + j] = c;
        split3(e.y, a, b, c);
        g_a0[row*KG + j + 1] = a; g_a1[row*KG + j + 1] = b; g_a2[row*KG + j + 1] = c;
    }
}

// ---------------- launch ------------------------------------------------------
extern "C" void kernel_launch(void* const* d_in, const int* in_sizes, int n_in,
                              void* d_out, int out_size)
{
    const float* eh    = (const float*)d_in[0];
    const float* ec    = (const float*)d_in[1];
    const float* emb   = (const float*)d_in[2];
    const float* w_ih  = (const float*)d_in[3];
    const float* w_hh  = (const float*)d_in[4];
    const float* b_ih  = (const float*)d_in[5];
    const float* b_hh  = (const float*)d_in[6];
    const float* w_out = (const float*)d_in[7];
    const float* b_out = (const float*)d_in[8];
    const int*   sos   = (const int*)d_in[9];
    float* out = (float*)d_out;

    cudaFuncSetAttribute(hmma_gemm<KL, 512, 1>,
                         cudaFuncAttributeMaxDynamicSharedMemorySize, SMEM_BYTES);
    cudaFuncSetAttribute(hmma_gemm<512, 0, 0>,
                         cudaFuncAttributeMaxDynamicSharedMemorySize, SMEM_BYTES);

    conv_wout_kernel<<<(int)(((size_t)VOCAB*KL/4 + 255)/256), 256>>>(w_out);
    conv_wg_kernel<<<(int)(((size_t)GATES4*KG/4 + 255)/256), 256>>>(w_ih, w_hh);
    init_kernel<<<(BATCH*VOCAB + 255)/256, 256>>>(eh, ec, emb, sos, out);

    for (int step = 1; step < MAXLEN; step++) {
        hmma_gemm<512, 0, 0><<<dim3(32, 3), 256, SMEM_BYTES>>>(nullptr, nullptr);
        lstm_kernel<<<(BATCH*HIDDEN)/256, 256>>>(b_ih, b_hh);
        hmma_gemm<KL, 512, 1><<<dim3(NTILES, 1), 256, SMEM_BYTES>>>(
            b_out, out + (size_t)step*BATCH*VOCAB);
        finalize_kernel<<<BATCH, 256>>>(emb);
    }
}

// round 4
// speedup vs baseline: 4.7129x; 2.7693x over previous
#include <cuda_runtime.h>
#include <cuda_fp16.h>
#include <math.h>
#include <stdint.h>

#define BATCH   128
#define HIDDEN  1024
#define EMBED   512
#define VOCAB   32000
#define MAXLEN  48
#define GATES4  4096
#define KL      1024          // logits K
#define KG      1536          // gates K (512 x + 1024 h)
#define NTILES  250           // logits N tiles of 128
#define KSPLIT  4             // gates split-K
#define STAGE_BYTES 65536     // 4 tiles (A0,A1,B0,B1) x 16KB
#define SMEM_BYTES  (3*STAGE_BYTES)

// ---------------- persistent device state (no allocation) --------------------
__device__ __align__(16) __half g_a0[BATCH*KG];   // A: cols [0,512)=x, [512,1536)=h
__device__ __align__(16) __half g_a1[BATCH*KG];
__device__ __align__(16) __half g_w0[(size_t)VOCAB*KL];
__device__ __align__(16) __half g_w1[(size_t)VOCAB*KL];
__device__ __align__(16) __half g_g0[(size_t)GATES4*KG];
__device__ __align__(16) __half g_g1[(size_t)GATES4*KG];
__device__ float g_c[BATCH*HIDDEN];
__device__ float g_part[KSPLIT*BATCH*GATES4];
__device__ float g_pval[NTILES*BATCH];
__device__ int   g_pidx[NTILES*BATCH];

// ---------------- ptx helpers (base-family PTX, sm_80+) ----------------------
__device__ __forceinline__ uint32_t smem_u32(const void* p) {
    uint32_t a;
    asm("{ .reg .u64 t; cvta.to.shared.u64 t, %1; cvt.u32.u64 %0, t; }" : "=r"(a) : "l"(p));
    return a;
}
__device__ __forceinline__ void cpa16(uint32_t dst, const void* src) {
    asm volatile("cp.async.cg.shared.global [%0], [%1], 16;" :: "r"(dst), "l"(src));
}
__device__ __forceinline__ void cpa_commit() {
    asm volatile("cp.async.commit_group;" ::: "memory");
}
template<int N> __device__ __forceinline__ void cpa_wait() {
    asm volatile("cp.async.wait_group %0;" :: "n"(N) : "memory");
}
__device__ __forceinline__ void ldsm4(uint32_t* r, uint32_t addr) {
    asm volatile("ldmatrix.sync.aligned.m8n8.x4.shared.b16 {%0,%1,%2,%3}, [%4];"
                 : "=r"(r[0]), "=r"(r[1]), "=r"(r[2]), "=r"(r[3]) : "r"(addr));
}
__device__ __forceinline__ void mma16816(float* c, const uint32_t* a, uint32_t b0, uint32_t b1) {
    asm volatile(
        "mma.sync.aligned.m16n8k16.row.col.f32.f16.f16.f32 "
        "{%0,%1,%2,%3}, {%4,%5,%6,%7}, {%8,%9}, {%0,%1,%2,%3};"
        : "+f"(c[0]), "+f"(c[1]), "+f"(c[2]), "+f"(c[3])
        : "r"(a[0]), "r"(a[1]), "r"(a[2]), "r"(a[3]), "r"(b0), "r"(b1));
}
__device__ __forceinline__ uint32_t swz(uint32_t off) { return off ^ ((off >> 3) & 0x70); }

__device__ __forceinline__ void split2(float x, __half& a, __half& b) {
    a = __float2half_rn(x);
    b = __float2half_rn(x - __half2float(a));
}

// ---------------- weight conversion ------------------------------------------
__global__ void conv_wout_kernel(const float* __restrict__ w) {
    size_t i4 = ((size_t)blockIdx.x * 256 + threadIdx.x) * 4;
    if (i4 >= (size_t)VOCAB * KL) return;
    float4 v = *(const float4*)&w[i4];
    __half a[4], b[4];
    split2(v.x, a[0], b[0]); split2(v.y, a[1], b[1]);
    split2(v.z, a[2], b[2]); split2(v.w, a[3], b[3]);
#pragma unroll
    for (int j = 0; j < 4; j++) { g_w0[i4+j] = a[j]; g_w1[i4+j] = b[j]; }
}
__global__ void conv_wg_kernel(const float* __restrict__ w_ih, const float* __restrict__ w_hh) {
    size_t i4 = ((size_t)blockIdx.x * 256 + threadIdx.x) * 4;
    if (i4 >= (size_t)GATES4 * KG) return;
    int n = (int)(i4 / KG), k = (int)(i4 % KG);
    float4 v;
    if (k < EMBED) v = *(const float4*)&w_ih[(size_t)n*EMBED + k];
    else           v = *(const float4*)&w_hh[(size_t)n*HIDDEN + (k - EMBED)];
    __half a[4], b[4];
    split2(v.x, a[0], b[0]); split2(v.y, a[1], b[1]);
    split2(v.z, a[2], b[2]); split2(v.w, a[3], b[3]);
#pragma unroll
    for (int j = 0; j < 4; j++) { g_g0[i4+j] = a[j]; g_g1[i4+j] = b[j]; }
}

// ---------------- init -------------------------------------------------------
__global__ void init_kernel(const float* __restrict__ eh, const float* __restrict__ ec,
                            const float* __restrict__ emb, const int* __restrict__ sos,
                            float* __restrict__ out0)
{
    int idx = blockIdx.x * 256 + threadIdx.x;
    if (idx < BATCH*HIDDEN) {
        int bb = idx >> 10, j = idx & 1023;
        __half a, b;
        split2(eh[idx], a, b);
        g_a0[bb*KG + 512 + j] = a; g_a1[bb*KG + 512 + j] = b;
        g_c[idx] = ec[idx];
    }
    if (idx < BATCH*EMBED) {
        int bb = idx >> 9, j = idx & 511;
        __half a, b;
        split2(emb[(size_t)sos[0]*EMBED + j], a, b);
        g_a0[bb*KG + j] = a; g_a1[bb*KG + j] = b;
    }
    if (idx < BATCH*VOCAB) out0[idx] = 0.0f;
}

// ---------------- split-fp16 HMMA GEMM ---------------------------------------
// C[128 x 128-tile] = A0*B0 + A0*B1 + A1*B0 (fp32 accum), 3-stage cp.async.
// MODE 0: gates (split-K over blockIdx.y -> g_part).
// MODE 1: logits (+bias, store, fused partial argmax).
template<int KLEN, int AOFF, int MODE>
__global__ __launch_bounds__(256, 1) void hmma_gemm(
    const float* __restrict__ bias, float* __restrict__ out)
{
    extern __shared__ char smem[];
    const uint32_t sbase = smem_u32(smem);
    const int tid  = threadIdx.x;
    const int lane = tid & 31;
    const int warp = tid >> 5;
    const int wm = warp >> 2, wn = warp & 3;
    const int m_base = wm * 64, n_base = wn * 32;
    const int n0     = blockIdx.x * 128;
    const int kStart = (MODE == 0) ? blockIdx.y * KLEN : 0;
    const int BSTRIDE = (MODE == 1) ? KL : KG;
    const int NC = KLEN / 64;

    const __half* Aptr[2] = { g_a0, g_a1 };
    const __half* Bptr[2];
    if (MODE == 1) { Bptr[0] = g_w0; Bptr[1] = g_w1; }
    else           { Bptr[0] = g_g0; Bptr[1] = g_g1; }

    auto load_stage = [&](int buf, int c) {
        uint32_t sdst = sbase + buf * STAGE_BYTES;
        const int aCol = AOFF + kStart + c * 64;
        const int bCol = kStart + c * 64;
#pragma unroll
        for (int i = 0; i < 16; i++) {
            const int tile = i >> 2;                      // 0:A0 1:A1 2:B0 3:B1
            const int rem = (i * 256 + tid) & 1023;
            const int row = rem >> 3, ch = rem & 7;
            const __half* src;
            if (tile < 2) src = Aptr[tile] + row * KG + aCol + ch * 8;
            else          src = Bptr[tile-2] + (size_t)(n0 + row) * BSTRIDE + bCol + ch * 8;
            cpa16(sdst + tile * 16384 + swz((uint32_t)(row * 128 + ch * 16)), src);
        }
    };

    float acc[4][4][4];
#pragma unroll
    for (int i = 0; i < 4; i++)
#pragma unroll
        for (int j = 0; j < 4; j++)
#pragma unroll
            for (int q = 0; q < 4; q++) acc[i][j][q] = 0.f;

    load_stage(0, 0); cpa_commit();
    load_stage(1, 1); cpa_commit();

#pragma unroll 1
    for (int c = 0; c < NC; c++) {
        if (c + 2 < NC)      { load_stage((c + 2) % 3, c + 2); cpa_commit(); cpa_wait<2>(); }
        else if (c + 1 < NC) { cpa_wait<1>(); }
        else                 { cpa_wait<0>(); }
        __syncthreads();

        const uint32_t sb  = sbase + (c % 3) * STAGE_BYTES;
        const uint32_t sA0 = sb, sA1 = sb + 16384, sB0 = sb + 32768, sB1 = sb + 49152;
#pragma unroll
        for (int ks = 0; ks < 4; ks++) {
            const uint32_t kb = (uint32_t)(ks * 32 + ((lane >> 4) << 4));
            uint32_t a0[4][4], a1[4][4], b0[2][4], b1[2][4];
#pragma unroll
            for (int mt = 0; mt < 4; mt++) {
                const uint32_t roff = swz((uint32_t)((m_base + mt*16 + (lane & 15)) * 128) + kb);
                ldsm4(a0[mt], sA0 + roff);
                ldsm4(a1[mt], sA1 + roff);
            }
#pragma unroll
            for (int nh = 0; nh < 2; nh++) {
                const uint32_t roff = swz((uint32_t)((n_base + nh*16 + (lane & 15)) * 128) + kb);
                ldsm4(b0[nh], sB0 + roff);
                ldsm4(b1[nh], sB1 + roff);
            }
#pragma unroll
            for (int mt = 0; mt < 4; mt++)
#pragma unroll
                for (int nt = 0; nt < 4; nt++) {
                    const int nh = nt >> 1, hi = nt & 1;
                    mma16816(acc[mt][nt], a0[mt], b0[nh][hi], b0[nh][hi + 2]);
                    mma16816(acc[mt][nt], a0[mt], b1[nh][hi], b1[nh][hi + 2]);
                    mma16816(acc[mt][nt], a1[mt], b0[nh][hi], b0[nh][hi + 2]);
                }
        }
        __syncthreads();
    }

    // -------------------------- epilogue ------------------------------------
    if (MODE == 0) {
        float* o = g_part + (size_t)blockIdx.y * BATCH * GATES4;
#pragma unroll
        for (int mt = 0; mt < 4; mt++) {
            const int r0 = m_base + mt * 16 + (lane >> 2);
#pragma unroll
            for (int nt = 0; nt < 4; nt++) {
                const int col = n0 + n_base + nt * 8 + (lane & 3) * 2;
                *(float2*)&o[(size_t)r0 * GATES4 + col]       = make_float2(acc[mt][nt][0], acc[mt][nt][1]);
                *(float2*)&o[(size_t)(r0 + 8) * GATES4 + col] = make_float2(acc[mt][nt][2], acc[mt][nt][3]);
            }
        }
    } else {
        float2 bv[4];
#pragma unroll
        for (int nt = 0; nt < 4; nt++)
            bv[nt] = *(const float2*)&bias[n0 + n_base + nt * 8 + (lane & 3) * 2];

        float* rv = (float*)smem;
        int*   ri = (int*)(smem + 4096);

#pragma unroll
        for (int mt = 0; mt < 4; mt++) {
#pragma unroll
            for (int half = 0; half < 2; half++) {
                const int row = m_base + mt * 16 + (lane >> 2) + half * 8;
                float best = -INFINITY; int bidx = 0;
#pragma unroll
                for (int nt = 0; nt < 4; nt++) {
                    const int col = n0 + n_base + nt * 8 + (lane & 3) * 2;
                    float v0 = acc[mt][nt][half*2]   + bv[nt].x;
                    float v1 = acc[mt][nt][half*2+1] + bv[nt].y;
                    *(float2*)&out[(size_t)row * VOCAB + col] = make_float2(v0, v1);
                    if (v0 > best) { best = v0; bidx = col; }
                    if (v1 > best) { best = v1; bidx = col + 1; }
                }
#pragma unroll
                for (int off = 1; off <= 2; off <<= 1) {
                    float ov = __shfl_xor_sync(0xffffffffu, best, off);
                    int   oi = __shfl_xor_sync(0xffffffffu, bidx, off);
                    if (ov > best || (ov == best && oi < bidx)) { best = ov; bidx = oi; }
                }
                if ((lane & 3) == 0) { rv[row * 4 + wn] = best; ri[row * 4 + wn] = bidx; }
            }
        }
        __syncthreads();
        if (tid < 128) {
            float best = rv[tid * 4]; int bidx = ri[tid * 4];
#pragma unroll
            for (int w = 1; w < 4; w++) {
                float ov = rv[tid * 4 + w]; int oi = ri[tid * 4 + w];
                if (ov > best || (ov == best && oi < bidx)) { best = ov; bidx = oi; }
            }
            g_pval[blockIdx.x * BATCH + tid] = best;
            g_pidx[blockIdx.x * BATCH + tid] = bidx;
        }
    }
}

// ---------------- LSTM elementwise (sums split-K partials) -------------------
__global__ void lstm_kernel(const float* __restrict__ b_ih, const float* __restrict__ b_hh)
{
    int idx = blockIdx.x * 256 + threadIdx.x;     // < 128*1024
    int b = idx >> 10, j = idx & 1023;
    const int o = b * GATES4 + j;
    float ig = b_ih[j]        + b_hh[j];
    float fg = b_ih[1024 + j] + b_hh[1024 + j];
    float gg = b_ih[2048 + j] + b_hh[2048 + j];
    float og = b_ih[3072 + j] + b_hh[3072 + j];
#pragma unroll
    for (int s = 0; s < KSPLIT; s++) {
        const float* P = g_part + (size_t)s * BATCH * GATES4;
        ig += P[o]; fg += P[o + 1024]; gg += P[o + 2048]; og += P[o + 3072];
    }
    float i_s = 1.f / (1.f + expf(-ig));
    float f_s = 1.f / (1.f + expf(-fg));
    float g_t = tanhf(gg);
    float o_s = 1.f / (1.f + expf(-og));
    float cc = f_s * g_c[idx] + i_s * g_t;
    g_c[idx] = cc;
    float h = o_s * tanhf(cc);
    __half a, bb;
    split2(h, a, bb);
    g_a0[b*KG + 512 + j] = a; g_a1[b*KG + 512 + j] = bb;
}

// ---------------- argmax finalize + embedding gather -------------------------
__global__ void finalize_kernel(const float* __restrict__ emb)
{
    int row = blockIdx.x;
    int t = threadIdx.x;
    __shared__ float sv[256];
    __shared__ int   si[256];
    __shared__ int   nstar;
    float v = -INFINITY; int id = 0x7fffffff;
    if (t < NTILES) { v = g_pval[t*BATCH + row]; id = g_pidx[t*BATCH + row]; }
    sv[t] = v; si[t] = id;
    __syncthreads();
    for (int s = 128; s > 0; s >>= 1) {
        if (t < s) {
            float ov = sv[t+s]; int oi = si[t+s];
            if (ov > sv[t] || (ov == sv[t] && oi < si[t])) { sv[t] = ov; si[t] = oi; }
        }
        __syncthreads();
    }
    if (t == 0) nstar = si[0];
    __syncthreads();
    {
        int j = t * 2;
        float2 e = *(const float2*)&emb[(size_t)nstar*EMBED + j];
        __half a, b;
        split2(e.x, a, b);
        g_a0[row*KG + j] = a; g_a1[row*KG + j] = b;
        split2(e.y, a, b);
        g_a0[row*KG + j + 1] = a; g_a1[row*KG + j + 1] = b;
    }
}

// ---------------- launch ------------------------------------------------------
extern "C" void kernel_launch(void* const* d_in, const int* in_sizes, int n_in,
                              void* d_out, int out_size)
{
    const float* eh    = (const float*)d_in[0];
    const float* ec    = (const float*)d_in[1];
    const float* emb   = (const float*)d_in[2];
    const float* w_ih  = (const float*)d_in[3];
    const float* w_hh  = (const float*)d_in[4];
    const float* b_ih  = (const float*)d_in[5];
    const float* b_hh  = (const float*)d_in[6];
    const float* w_out = (const float*)d_in[7];
    const float* b_out = (const float*)d_in[8];
    const int*   sos   = (const int*)d_in[9];
    float* out = (float*)d_out;

    cudaFuncSetAttribute(hmma_gemm<KL, 512, 1>,
                         cudaFuncAttributeMaxDynamicSharedMemorySize, SMEM_BYTES);
    cudaFuncSetAttribute(hmma_gemm<KG/KSPLIT, 0, 0>,
                         cudaFuncAttributeMaxDynamicSharedMemorySize, SMEM_BYTES);

    conv_wout_kernel<<<(int)(((size_t)VOCAB*KL/4 + 255)/256), 256>>>(w_out);
    conv_wg_kernel<<<(int)(((size_t)GATES4*KG/4 + 255)/256), 256>>>(w_ih, w_hh);
    init_kernel<<<(BATCH*VOCAB + 255)/256, 256>>>(eh, ec, emb, sos, out);

    for (int step = 1; step < MAXLEN; step++) {
        hmma_gemm<KG/KSPLIT, 0, 0><<<dim3(32, KSPLIT), 256, SMEM_BYTES>>>(nullptr, nullptr);
        lstm_kernel<<<(BATCH*HIDDEN)/256, 256>>>(b_ih, b_hh);
        hmma_gemm<KL, 512, 1><<<dim3(NTILES, 1), 256, SMEM_BYTES>>>(
            b_out, out + (size_t)step*BATCH*VOCAB);
        finalize_kernel<<<BATCH, 256>>>(emb);
    }
}